// round 8
// baseline (speedup 1.0000x reference)
#include <cuda_runtime.h>
#include <cuda_fp16.h>
#include <math.h>

#define T_LEN 8192
#define DM    1536
#define NH    16
#define NKV   4
#define HD    96
#define KVW   (NKV*HD)   // 384
#define QW    (NH*HD)    // 1536
#define W2    256
#define KW2   (DM/2)     // 768 h2 words per A row

// ---------------- scratch (device globals; no allocation allowed) ----------
__device__ float    g_qs[(size_t)T_LEN*QW];
__device__ float    g_ks[(size_t)T_LEN*KVW];
__device__ float    g_vs[(size_t)T_LEN*KVW];
__device__ float    g_kg[(size_t)T_LEN*KVW];
__device__ float    g_vg[(size_t)T_LEN*KVW];
__device__ float    g_qg0[QW];
__device__ unsigned g_xh[(size_t)T_LEN*KW2];      // x packed h2
__device__ unsigned g_ctxh[(size_t)T_LEN*KW2];    // ctx packed h2
__device__ unsigned g_wqsh[(size_t)KW2*QW];
__device__ unsigned g_wksh[(size_t)KW2*KVW];
__device__ unsigned g_wvsh[(size_t)KW2*KVW];
__device__ unsigned g_wkgh[(size_t)KW2*KVW];
__device__ unsigned g_wvgh[(size_t)KW2*KVW];
__device__ unsigned g_woh[(size_t)KW2*QW];

// ---------------- helpers ---------------------------------------------------
__device__ __forceinline__ unsigned f2tf(float x) {
    unsigned u; asm("cvt.rna.tf32.f32 %0, %1;" : "=r"(u) : "f"(x)); return u;
}
__device__ __forceinline__ unsigned packh2(float a, float b) {
    __half2 h = __floats2half2_rn(a, b);
    return *(unsigned*)&h;
}
__device__ __forceinline__ void mma_tf32(float c[4], const unsigned a[4], const unsigned b[2]) {
    asm volatile("mma.sync.aligned.m16n8k8.row.col.f32.tf32.tf32.f32 "
        "{%0,%1,%2,%3}, {%4,%5,%6,%7}, {%8,%9}, {%0,%1,%2,%3};"
        : "+f"(c[0]), "+f"(c[1]), "+f"(c[2]), "+f"(c[3])
        : "r"(a[0]), "r"(a[1]), "r"(a[2]), "r"(a[3]), "r"(b[0]), "r"(b[1]));
}
__device__ __forceinline__ void mma_f16(float c[4], const unsigned a[4], const unsigned b[2]) {
    asm volatile("mma.sync.aligned.m16n8k16.row.col.f32.f16.f16.f32 "
        "{%0,%1,%2,%3}, {%4,%5,%6,%7}, {%8,%9}, {%0,%1,%2,%3};"
        : "+f"(c[0]), "+f"(c[1]), "+f"(c[2]), "+f"(c[3])
        : "r"(a[0]), "r"(a[1]), "r"(a[2]), "r"(a[3]), "r"(b[0]), "r"(b[1]));
}
__device__ __forceinline__ void cp16(void* s, const void* g) {
    unsigned sa = (unsigned)__cvta_generic_to_shared(s);
    asm volatile("cp.async.cg.shared.global [%0], [%1], 16;" :: "r"(sa), "l"(g));
}

// ---------------- pack kernels ---------------------------------------------
// pack along contiguous dim: out[i] = h2(in[2i], in[2i+1])
__global__ void pack_rows(const float* __restrict__ in, unsigned* __restrict__ out, int total) {
    int i = blockIdx.x * 256 + threadIdx.x;
    if (i < total) {
        float2 v = *(const float2*)&in[2 * i];
        out[i] = packh2(v.x, v.y);
    }
}
// pack along K (row) dim of [K][N] row-major: out[kw*N+n] = h2(in[2kw*N+n], in[(2kw+1)*N+n])
__global__ void pack_cols(const float* __restrict__ in, unsigned* __restrict__ out,
                          int N, int total) {
    int i = blockIdx.x * 256 + threadIdx.x;
    if (i < total) {
        int kw = i / N, n = i - kw * N;
        out[i] = packh2(in[(size_t)(2 * kw) * N + n], in[(size_t)(2 * kw + 1) * N + n]);
    }
}

// ---------------- FP16 GEMM body: 3-stage cp.async pipeline ----------------
// C[M,N] = A[M,K] @ B[K,N] with A,B pre-packed h2 along K. 128x128 tile, BK=64.
#define NSTAGE 3
#define AHSTR 36                 // 128 rows x 32 h2-words, stride 36
#define BHSTR 136                // 32 h2-rows x 128 cols, stride 136
#define AH_TILE (128*AHSTR)      // 4608 words
#define BH_TILE (32*BHSTR)       // 4352 words
#define GEMM_SMEM (NSTAGE*(AH_TILE+BH_TILE)*4)   // 107520 bytes

__device__ __forceinline__ void gemm_body(const unsigned* __restrict__ Ah,
                                          const unsigned* __restrict__ Bh,
                                          float* __restrict__ C,
                                          int N, int row0, int col0) {
    extern __shared__ unsigned smw[];
    unsigned* As = smw;
    unsigned* Bs = smw + NSTAGE * AH_TILE;
    int tid = threadIdx.x, lane = tid & 31, warp = tid >> 5;
    int wm = (warp >> 1) * 32, wn = (warp & 1) * 64;
    int gid = lane >> 2, qid = lane & 3;

    float c[2][8][4];
#pragma unroll
    for (int mt = 0; mt < 2; mt++)
#pragma unroll
        for (int nt = 0; nt < 8; nt++)
#pragma unroll
            for (int i = 0; i < 4; i++) c[mt][nt][i] = 0.f;

    const int nk = KW2 / 32;   // 24 tiles of 32 h2-words (64 k)

    auto load_stage = [&](int st, int kw0) {
        unsigned* Asm = As + st * AH_TILE;
        unsigned* Bsm = Bs + st * BH_TILE;
#pragma unroll
        for (int i = 0; i < 4; i++) {
            int f = tid + 256 * i;
            int r = f >> 3, wq = (f & 7) * 4;
            cp16(&Asm[r * AHSTR + wq], &Ah[(size_t)(row0 + r) * KW2 + kw0 + wq]);
        }
#pragma unroll
        for (int i = 0; i < 4; i++) {
            int f = tid + 256 * i;
            int kw = f >> 5, c4 = (f & 31) * 4;
            cp16(&Bsm[kw * BHSTR + c4], &Bh[(size_t)(kw0 + kw) * N + col0 + c4]);
        }
        asm volatile("cp.async.commit_group;");
    };

    load_stage(0, 0);
    load_stage(1, 32);

    for (int it = 0; it < nk; it++) {
        if (it + 1 < nk) asm volatile("cp.async.wait_group 1;");
        else             asm volatile("cp.async.wait_group 0;");
        __syncthreads();
        if (it + 2 < nk) load_stage((it + 2) % NSTAGE, (it + 2) * 32);

        unsigned* Asm = As + (it % NSTAGE) * AH_TILE;
        unsigned* Bsm = Bs + (it % NSTAGE) * BH_TILE;
#pragma unroll
        for (int kk = 0; kk < 4; kk++) {
            int kc = kk * 8;
            unsigned a[2][4], b[8][2];
#pragma unroll
            for (int mt = 0; mt < 2; mt++) {
                int row = wm + mt * 16 + gid;
                a[mt][0] = Asm[row * AHSTR + kc + qid];
                a[mt][1] = Asm[(row + 8) * AHSTR + kc + qid];
                a[mt][2] = Asm[row * AHSTR + kc + qid + 4];
                a[mt][3] = Asm[(row + 8) * AHSTR + kc + qid + 4];
            }
#pragma unroll
            for (int nt = 0; nt < 8; nt++) {
                int col = wn + nt * 8 + gid;
                b[nt][0] = Bsm[(kc + qid) * BHSTR + col];
                b[nt][1] = Bsm[(kc + qid + 4) * BHSTR + col];
            }
#pragma unroll
            for (int mt = 0; mt < 2; mt++)
#pragma unroll
                for (int nt = 0; nt < 8; nt++)
                    mma_f16(c[mt][nt], a[mt], b[nt]);
        }
        __syncthreads();
    }
#pragma unroll
    for (int mt = 0; mt < 2; mt++) {
        int r = row0 + wm + mt * 16 + gid;
#pragma unroll
        for (int nt = 0; nt < 8; nt++) {
            int cc = col0 + wn + nt * 8 + 2 * qid;
            *(float2*)&C[(size_t)r * N + cc]       = make_float2(c[mt][nt][0], c[mt][nt][1]);
            *(float2*)&C[(size_t)(r + 8) * N + cc] = make_float2(c[mt][nt][2], c[mt][nt][3]);
        }
    }
}

__global__ __launch_bounds__(256)
void proj_gemm(const unsigned* __restrict__ xh,
               const unsigned* __restrict__ Wqs, const unsigned* __restrict__ Wks,
               const unsigned* __restrict__ Wvs, const unsigned* __restrict__ Wkg,
               const unsigned* __restrict__ Wvg,
               float* qs, float* ks, float* vs, float* kg, float* vg) {
    int id = blockIdx.x;
    const unsigned* B; float* C; int N, rb, cb;
    if (id < 768) {
        B = Wqs; C = qs; N = QW; cb = id % 12; rb = id / 12;
    } else {
        int r = id - 768;
        int w = r / 192; r -= w * 192;
        cb = r % 3; rb = r / 3; N = KVW;
        if      (w == 0) { B = Wks; C = ks; }
        else if (w == 1) { B = Wvs; C = vs; }
        else if (w == 2) { B = Wkg; C = kg; }
        else             { B = Wvg; C = vg; }
    }
    gemm_body(xh, B, C, N, rb * 128, cb * 128);
}

__global__ __launch_bounds__(256)
void out_gemm(const unsigned* __restrict__ ctxh, const unsigned* __restrict__ Woh,
              float* __restrict__ out) {
    int id = blockIdx.x;
    int cb = id % 12, rb = id / 12;
    gemm_body(ctxh, Woh, out, QW, rb * 128, cb * 128);
}

// ---------------- qg row 0 only ---------------------------------------------
__global__ __launch_bounds__(256)
void qg0_kernel(const float* __restrict__ x, const float* __restrict__ W,
                float* __restrict__ out) {
    __shared__ float xs[DM];
    int j = blockIdx.x * 256 + threadIdx.x;
    for (int k = threadIdx.x; k < DM; k += 256) xs[k] = x[k];
    __syncthreads();
    float a0 = 0.f, a1 = 0.f, a2 = 0.f, a3 = 0.f;
#pragma unroll 4
    for (int k = 0; k < DM; k += 4) {
        a0 += xs[k]     * W[(size_t)k       * QW + j];
        a1 += xs[k + 1] * W[(size_t)(k + 1) * QW + j];
        a2 += xs[k + 2] * W[(size_t)(k + 2) * QW + j];
        a3 += xs[k + 3] * W[(size_t)(k + 3) * QW + j];
    }
    out[j] = (a0 + a1) + (a2 + a3);
}

// ---------------- RoPE ------------------------------------------------------
__global__ void rope_kernel(float* __restrict__ x,
                            const float* __restrict__ cosf,
                            const float* __restrict__ sinf, int H) {
    int idx = blockIdx.x * blockDim.x + threadIdx.x;
    int total = T_LEN * H * (HD / 2);
    if (idx >= total) return;
    int p = idx % (HD / 2);
    int h = (idx / (HD / 2)) % H;
    int t = idx / ((HD / 2) * H);
    float c = cosf[t * (HD / 2) + p];
    float s = sinf[t * (HD / 2) + p];
    float* base = x + ((size_t)t * H + h) * HD + 2 * p;
    float xe = base[0], xo = base[1];
    base[0] = xe * c - xo * s;
    base[1] = xe * s + xo * c;
}

// ---------------- tensor-core flash attention (writes packed h2 ctx) -------
#define QSTR 100
#define KSTR 100
#define VSTR 104
#define PSTR 132
#define ATTN_SMEM ((128*QSTR + 128*KSTR + 128*VSTR + 128*PSTR + 128 + 96) * 4)

__global__ __launch_bounds__(256)
void flash_attn_kernel(const float* __restrict__ qs_g, const float* __restrict__ ks_g,
                       const float* __restrict__ vs_g, const float* __restrict__ kg,
                       const float* __restrict__ vg, unsigned* __restrict__ ctxh) {
    extern __shared__ unsigned smu[];
    unsigned* Qs = smu;
    unsigned* Ks = Qs + 128 * QSTR;
    unsigned* Vs = Ks + 128 * KSTR;
    unsigned* Ps = Vs + 128 * VSTR;
    float* sg  = (float*)(Ps + 128 * PSTR);
    float* vgs = sg + 128;

    int tid = threadIdx.x, lane = tid & 31, warp = tid >> 5;
    int gid = lane >> 2, qid = lane & 3;
    int h = blockIdx.y, kvh = h >> 2;
    int q0 = blockIdx.x * 128;
    const float scale = rsqrtf((float)HD);
    int row = warp * 16 + gid;

#pragma unroll
    for (int i = 0; i < 12; i++) {
        int f = tid + 256 * i;
        int r = f / 24, c4 = (f % 24) * 4;
        float4 v = *(const float4*)&qs_g[((size_t)(q0 + r) * NH + h) * HD + c4];
        unsigned* p = &Qs[r * QSTR + c4];
        p[0] = f2tf(v.x); p[1] = f2tf(v.y); p[2] = f2tf(v.z); p[3] = f2tf(v.w);
    }
    {
        int qi = tid >> 1, half = tid & 1;
        float part = 0.f;
        const float* qrow = &qs_g[((size_t)(q0 + qi) * NH + h) * HD + half * 48];
        const float* krow = &kg[(size_t)kvh * HD + half * 48];
#pragma unroll
        for (int d = 0; d < 48; d++) part += qrow[d] * krow[d];
        part += __shfl_xor_sync(0xffffffffu, part, 1);
        if (half == 0) sg[qi] = part * scale;
    }
    if (tid < 96) vgs[tid] = vg[(size_t)kvh * HD + tid];

    float m0 = -1e9f, m1 = -1e9f, l0 = 0.f, l1 = 0.f;
    float o[12][4];
#pragma unroll
    for (int nt = 0; nt < 12; nt++)
#pragma unroll
        for (int i = 0; i < 4; i++) o[nt][i] = 0.f;

    __syncthreads();

    for (int kt = 0; kt < 3; kt++) {
        int kstart = q0 - W2 + kt * 128;
#pragma unroll
        for (int i = 0; i < 12; i++) {
            int f = tid + 256 * i;
            int r = f / 24, c4 = (f % 24) * 4;
            int krow = kstart + r;
            float4 kv = make_float4(0.f, 0.f, 0.f, 0.f), vv = kv;
            if (krow >= 0) {
                kv = *(const float4*)&ks_g[((size_t)krow * NKV + kvh) * HD + c4];
                vv = *(const float4*)&vs_g[((size_t)krow * NKV + kvh) * HD + c4];
            }
            unsigned* pk = &Ks[r * KSTR + c4];
            pk[0] = f2tf(kv.x); pk[1] = f2tf(kv.y); pk[2] = f2tf(kv.z); pk[3] = f2tf(kv.w);
            unsigned* pv = &Vs[r * VSTR + c4];
            pv[0] = f2tf(vv.x); pv[1] = f2tf(vv.y); pv[2] = f2tf(vv.z); pv[3] = f2tf(vv.w);
        }
        __syncthreads();

        float s[16][4];
#pragma unroll
        for (int nt = 0; nt < 16; nt++)
#pragma unroll
            for (int i = 0; i < 4; i++) s[nt][i] = 0.f;
#pragma unroll
        for (int ks = 0; ks < 12; ks++) {
            unsigned a[4];
            a[0] = Qs[row * QSTR + ks * 8 + qid];
            a[1] = Qs[(row + 8) * QSTR + ks * 8 + qid];
            a[2] = Qs[row * QSTR + ks * 8 + qid + 4];
            a[3] = Qs[(row + 8) * QSTR + ks * 8 + qid + 4];
#pragma unroll
            for (int nt = 0; nt < 16; nt++) {
                unsigned b[2];
                int col = nt * 8 + gid;
                b[0] = Ks[col * KSTR + ks * 8 + qid];
                b[1] = Ks[col * KSTR + ks * 8 + qid + 4];
                mma_tf32(s[nt], a, b);
            }
        }

        int t0 = q0 + row, t1 = t0 + 8;
        float tmax0 = -1e9f, tmax1 = -1e9f;
#pragma unroll
        for (int nt = 0; nt < 16; nt++) {
            int cb = kstart + nt * 8 + 2 * qid;
#pragma unroll
            for (int cc = 0; cc < 2; cc++) {
                int kp = cb + cc;
                bool v0 = (kp >= 1) && (kp <= t0) && (kp >= t0 - W2);
                bool v1 = (kp >= 1) && (kp <= t1) && (kp >= t1 - W2);
                s[nt][cc]     = v0 ? s[nt][cc] * scale     : -1e9f;
                s[nt][cc + 2] = v1 ? s[nt][cc + 2] * scale : -1e9f;
                tmax0 = fmaxf(tmax0, s[nt][cc]);
                tmax1 = fmaxf(tmax1, s[nt][cc + 2]);
            }
        }
        tmax0 = fmaxf(tmax0, __shfl_xor_sync(0xffffffffu, tmax0, 1));
        tmax0 = fmaxf(tmax0, __shfl_xor_sync(0xffffffffu, tmax0, 2));
        tmax1 = fmaxf(tmax1, __shfl_xor_sync(0xffffffffu, tmax1, 1));
        tmax1 = fmaxf(tmax1, __shfl_xor_sync(0xffffffffu, tmax1, 2));
        float mn0 = fmaxf(m0, tmax0), mn1 = fmaxf(m1, tmax1);
        float corr0 = __expf(m0 - mn0), corr1 = __expf(m1 - mn1);
        l0 *= corr0; l1 *= corr1;
#pragma unroll
        for (int nt = 0; nt < 12; nt++) {
            o[nt][0] *= corr0; o[nt][1] *= corr0;
            o[nt][2] *= corr1; o[nt][3] *= corr1;
        }
        float sum0 = 0.f, sum1 = 0.f;
#pragma unroll
        for (int nt = 0; nt < 16; nt++) {
            int cb = nt * 8 + 2 * qid;
#pragma unroll
            for (int cc = 0; cc < 2; cc++) {
                float p0 = __expf(s[nt][cc] - mn0);
                float p1 = __expf(s[nt][cc + 2] - mn1);
                sum0 += p0; sum1 += p1;
                Ps[row * PSTR + cb + cc]       = f2tf(p0);
                Ps[(row + 8) * PSTR + cb + cc] = f2tf(p1);
            }
        }
        sum0 += __shfl_xor_sync(0xffffffffu, sum0, 1);
        sum0 += __shfl_xor_sync(0xffffffffu, sum0, 2);
        sum1 += __shfl_xor_sync(0xffffffffu, sum1, 1);
        sum1 += __shfl_xor_sync(0xffffffffu, sum1, 2);
        l0 += sum0; l1 += sum1;
        m0 = mn0; m1 = mn1;
        __syncwarp();

#pragma unroll
        for (int ks = 0; ks < 16; ks++) {
            unsigned a[4];
            a[0] = Ps[row * PSTR + ks * 8 + qid];
            a[1] = Ps[(row + 8) * PSTR + ks * 8 + qid];
            a[2] = Ps[row * PSTR + ks * 8 + qid + 4];
            a[3] = Ps[(row + 8) * PSTR + ks * 8 + qid + 4];
#pragma unroll
            for (int nt = 0; nt < 12; nt++) {
                unsigned b[2];
                int col = nt * 8 + gid;
                b[0] = Vs[(ks * 8 + qid) * VSTR + col];
                b[1] = Vs[(ks * 8 + qid + 4) * VSTR + col];
                mma_tf32(o[nt], a, b);
            }
        }
        __syncthreads();
    }

    // global key (position 0) + packed h2 epilogue
    {
        float sg0 = sg[row], sg1 = sg[row + 8];
        float mn0 = fmaxf(m0, sg0), mn1 = fmaxf(m1, sg1);
        float corr0 = __expf(m0 - mn0), corr1 = __expf(m1 - mn1);
        float pg0 = __expf(sg0 - mn0), pg1 = __expf(sg1 - mn1);
        l0 = l0 * corr0 + pg0;
        l1 = l1 * corr1 + pg1;
        float inv0 = 1.f / l0, inv1 = 1.f / l1;
        int t0 = q0 + row, t1 = t0 + 8;
#pragma unroll
        for (int nt = 0; nt < 12; nt++) {
            int d = nt * 8 + 2 * qid;
            float v0 = vgs[d], v1 = vgs[d + 1];
            unsigned w0 = packh2((o[nt][0] * corr0 + pg0 * v0) * inv0,
                                 (o[nt][1] * corr0 + pg0 * v1) * inv0);
            unsigned w1 = packh2((o[nt][2] * corr1 + pg1 * v0) * inv1,
                                 (o[nt][3] * corr1 + pg1 * v1) * inv1);
            ctxh[(size_t)t0 * KW2 + h * 48 + nt * 4 + qid] = w0;
            ctxh[(size_t)t1 * KW2 + h * 48 + nt * 4 + qid] = w1;
        }
    }
}

// ---------------- global row: q@pos0 (qg) over all T kg keys --------------
__global__ __launch_bounds__(192)
void global_row_kernel(const float* __restrict__ qg, const float* __restrict__ kg,
                       const float* __restrict__ vg, unsigned* __restrict__ ctxh) {
    __shared__ float p[T_LEN];
    __shared__ float red[256];
    int h = blockIdx.x, kvh = h >> 2, tid = threadIdx.x;
    float q[HD];
#pragma unroll
    for (int d = 0; d < HD; d++) q[d] = qg[(size_t)h * HD + d];
    const float scale = rsqrtf((float)HD);

    float lm = -1e30f;
    for (int t = tid; t < T_LEN; t += 192) {
        float s = 0.f;
#pragma unroll
        for (int d = 0; d < HD; d++) s += q[d] * kg[((size_t)t * NKV + kvh) * HD + d];
        s *= scale;
        p[t] = s;
        lm = fmaxf(lm, s);
    }
    red[tid] = lm;
    if (tid < 64) red[192 + tid] = -1e30f;
    __syncthreads();
    for (int o = 128; o > 0; o >>= 1) {
        if (tid < o) red[tid] = fmaxf(red[tid], red[tid + o]);
        __syncthreads();
    }
    float m = red[0];
    __syncthreads();

    float ll = 0.f;
    for (int t = tid; t < T_LEN; t += 192) {
        float e = __expf(p[t] - m);
        p[t] = e;
        ll += e;
    }
    red[tid] = ll;
    if (tid < 64) red[192 + tid] = 0.f;
    __syncthreads();
    for (int o = 128; o > 0; o >>= 1) {
        if (tid < o) red[tid] += red[tid + o];
        __syncthreads();
    }
    float inv = 1.f / red[0];
    __syncthreads();

    int d = tid % 96, g = tid / 96;
    float acc0 = 0.f, acc1 = 0.f, acc2 = 0.f, acc3 = 0.f;
    for (int t = g; t < T_LEN; t += 8) {
        acc0 += p[t]     * vg[((size_t)t       * NKV + kvh) * HD + d];
        acc1 += p[t + 2] * vg[((size_t)(t + 2) * NKV + kvh) * HD + d];
        acc2 += p[t + 4] * vg[((size_t)(t + 4) * NKV + kvh) * HD + d];
        acc3 += p[t + 6] * vg[((size_t)(t + 6) * NKV + kvh) * HD + d];
    }
    red[tid] = acc0 + acc1 + acc2 + acc3;
    __syncthreads();
    // pack t=0 row as h2 (overwrites flash output for position 0)
    if (tid < 48) {
        int d0 = 2 * tid;
        float f0 = (red[d0]     + red[96 + d0])     * inv;
        float f1 = (red[d0 + 1] + red[96 + d0 + 1]) * inv;
        ctxh[(size_t)0 * KW2 + h * 48 + tid] = packh2(f0, f1);
    }
}

// ---------------- launch ---------------------------------------------------
extern "C" void kernel_launch(void* const* d_in, const int* in_sizes, int n_in,
                              void* d_out, int out_size) {
    const float* x    = (const float*)d_in[0];
    const float* cosf = (const float*)d_in[1];
    const float* sinf = (const float*)d_in[2];
    // d_in[3] = position_ids (arange, unused)
    const float* W_qs = (const float*)d_in[4];
    const float* W_ks = (const float*)d_in[5];
    const float* W_vs = (const float*)d_in[6];
    const float* W_qg = (const float*)d_in[7];
    const float* W_kg = (const float*)d_in[8];
    const float* W_vg = (const float*)d_in[9];
    const float* W_o  = (const float*)d_in[10];
    float* out = (float*)d_out;

    float *qs, *ks, *vs, *kg, *vg, *qg0;
    unsigned *xh, *ctxh, *wqsh, *wksh, *wvsh, *wkgh, *wvgh, *woh;
    cudaGetSymbolAddress((void**)&qs,   g_qs);
    cudaGetSymbolAddress((void**)&ks,   g_ks);
    cudaGetSymbolAddress((void**)&vs,   g_vs);
    cudaGetSymbolAddress((void**)&kg,   g_kg);
    cudaGetSymbolAddress((void**)&vg,   g_vg);
    cudaGetSymbolAddress((void**)&qg0,  g_qg0);
    cudaGetSymbolAddress((void**)&xh,   g_xh);
    cudaGetSymbolAddress((void**)&ctxh, g_ctxh);
    cudaGetSymbolAddress((void**)&wqsh, g_wqsh);
    cudaGetSymbolAddress((void**)&wksh, g_wksh);
    cudaGetSymbolAddress((void**)&wvsh, g_wvsh);
    cudaGetSymbolAddress((void**)&wkgh, g_wkgh);
    cudaGetSymbolAddress((void**)&wvgh, g_wvgh);
    cudaGetSymbolAddress((void**)&woh,  g_woh);

    cudaFuncSetAttribute(proj_gemm, cudaFuncAttributeMaxDynamicSharedMemorySize, GEMM_SMEM);
    cudaFuncSetAttribute(out_gemm,  cudaFuncAttributeMaxDynamicSharedMemorySize, GEMM_SMEM);
    cudaFuncSetAttribute(flash_attn_kernel, cudaFuncAttributeMaxDynamicSharedMemorySize, ATTN_SMEM);

    // ---- pack inputs to h2 ----
    int xtot = T_LEN * KW2;
    pack_rows<<<(xtot + 255) / 256, 256>>>(x, xh, xtot);
    int wq_tot = KW2 * QW, wn_tot = KW2 * KVW;
    pack_cols<<<(wq_tot + 255) / 256, 256>>>(W_qs, wqsh, QW, wq_tot);
    pack_cols<<<(wn_tot + 255) / 256, 256>>>(W_ks, wksh, KVW, wn_tot);
    pack_cols<<<(wn_tot + 255) / 256, 256>>>(W_vs, wvsh, KVW, wn_tot);
    pack_cols<<<(wn_tot + 255) / 256, 256>>>(W_kg, wkgh, KVW, wn_tot);
    pack_cols<<<(wn_tot + 255) / 256, 256>>>(W_vg, wvgh, KVW, wn_tot);
    pack_cols<<<(wq_tot + 255) / 256, 256>>>(W_o,  woh,  QW, wq_tot);

    proj_gemm<<<1536, 256, GEMM_SMEM>>>(xh, wqsh, wksh, wvsh, wkgh, wvgh,
                                        qs, ks, vs, kg, vg);
    qg0_kernel<<<QW / 256, 256>>>(x, W_qg, qg0);

    int pairs16 = T_LEN * NH * (HD / 2);
    int pairs4  = T_LEN * NKV * (HD / 2);
    rope_kernel<<<(pairs16 + 255) / 256, 256>>>(qs, cosf, sinf, NH);
    rope_kernel<<<(pairs4  + 255) / 256, 256>>>(ks, cosf, sinf, NKV);
    rope_kernel<<<(pairs4  + 255) / 256, 256>>>(kg, cosf, sinf, NKV);

    flash_attn_kernel<<<dim3(T_LEN / 128, NH), 256, ATTN_SMEM>>>(qs, ks, vs, kg, vg, ctxh);

    global_row_kernel<<<NH, 192>>>(qg0, kg, vg, ctxh);

    out_gemm<<<768, 256, GEMM_SMEM>>>(ctxh, woh, out);
}

// round 10
// speedup vs baseline: 1.2166x; 1.2166x over previous
#include <cuda_runtime.h>
#include <cuda_fp16.h>
#include <math.h>

#define T_LEN 8192
#define DM    1536
#define NH    16
#define NKV   4
#define HD    96
#define KVW   (NKV*HD)   // 384
#define QW    (NH*HD)    // 1536
#define W2    256

// ---------------- scratch (device globals; no allocation allowed) ----------
__device__ float    g_qs[(size_t)T_LEN*QW];
__device__ float    g_ks[(size_t)T_LEN*KVW];
__device__ float    g_vs[(size_t)T_LEN*KVW];
__device__ float    g_kg[(size_t)T_LEN*KVW];
__device__ float    g_vg[(size_t)T_LEN*KVW];
__device__ float    g_qg0[QW];
__device__ unsigned g_xt[(size_t)T_LEN*DM];      // x as tf32 bits
__device__ unsigned g_ctxt[(size_t)T_LEN*QW];    // ctx as tf32 bits
__device__ unsigned g_wqst[(size_t)DM*QW];
__device__ unsigned g_wkst[(size_t)DM*KVW];
__device__ unsigned g_wvst[(size_t)DM*KVW];
__device__ unsigned g_wkgt[(size_t)DM*KVW];
__device__ unsigned g_wvgt[(size_t)DM*KVW];
__device__ unsigned g_wot[(size_t)DM*QW];

// ---------------- helpers ---------------------------------------------------
__device__ __forceinline__ unsigned f2tf(float x) {
    unsigned u; asm("cvt.rna.tf32.f32 %0, %1;" : "=r"(u) : "f"(x)); return u;
}
__device__ __forceinline__ void mma_tf32(float c[4], const unsigned a[4], const unsigned b[2]) {
    asm volatile("mma.sync.aligned.m16n8k8.row.col.f32.tf32.tf32.f32 "
        "{%0,%1,%2,%3}, {%4,%5,%6,%7}, {%8,%9}, {%0,%1,%2,%3};"
        : "+f"(c[0]), "+f"(c[1]), "+f"(c[2]), "+f"(c[3])
        : "r"(a[0]), "r"(a[1]), "r"(a[2]), "r"(a[3]), "r"(b[0]), "r"(b[1]));
}
__device__ __forceinline__ void cp16(void* s, const void* g) {
    unsigned sa = (unsigned)__cvta_generic_to_shared(s);
    asm volatile("cp.async.cg.shared.global [%0], [%1], 16;" :: "r"(sa), "l"(g));
}

// ---------------- elementwise fp32 -> tf32-bits pack -----------------------
__global__ void pack_tf32(const float* __restrict__ in, unsigned* __restrict__ out,
                          int total4) {
    int i = blockIdx.x * 256 + threadIdx.x;
    if (i < total4) {
        float4 v = *(const float4*)&in[4 * i];
        uint4 u = make_uint4(f2tf(v.x), f2tf(v.y), f2tf(v.z), f2tf(v.w));
        *(uint4*)&out[4 * i] = u;
    }
}

// ---------------- TF32 GEMM body: 3-stage cp.async pipeline ----------------
// Inputs are pre-converted tf32 bits; inner loop is pure LDS + MMA.
#define NSTAGE 3
#define ASTR 36
#define BSTR 136
#define A_TILE (128*ASTR)
#define B_TILE (32*BSTR)
#define GEMM_SMEM (NSTAGE*(A_TILE+B_TILE)*4)   // 107520 bytes

__device__ __forceinline__ void gemm_body(const unsigned* __restrict__ A,
                                          const unsigned* __restrict__ B,
                                          float* __restrict__ C,
                                          int N, int row0, int col0) {
    extern __shared__ unsigned sm[];
    unsigned* As = sm;
    unsigned* Bs = sm + NSTAGE * A_TILE;
    const int K = DM;
    int tid = threadIdx.x, lane = tid & 31, warp = tid >> 5;
    int wm = (warp >> 1) * 32, wn = (warp & 1) * 64;
    int gid = lane >> 2, qid = lane & 3;

    float c[2][8][4];
#pragma unroll
    for (int mt = 0; mt < 2; mt++)
#pragma unroll
        for (int nt = 0; nt < 8; nt++)
#pragma unroll
            for (int i = 0; i < 4; i++) c[mt][nt][i] = 0.f;

    const int nk = K / 32;

    auto load_stage = [&](int st, int k0) {
        unsigned* Asm = As + st * A_TILE;
        unsigned* Bsm = Bs + st * B_TILE;
#pragma unroll
        for (int i = 0; i < 4; i++) {
            int f = tid + 256 * i;
            int r = f >> 3, kq = (f & 7) * 4;
            cp16(&Asm[r * ASTR + kq], &A[(size_t)(row0 + r) * K + k0 + kq]);
        }
#pragma unroll
        for (int i = 0; i < 4; i++) {
            int f = tid + 256 * i;
            int r = f >> 5, c4 = (f & 31) * 4;
            cp16(&Bsm[r * BSTR + c4], &B[(size_t)(k0 + r) * N + col0 + c4]);
        }
        asm volatile("cp.async.commit_group;");
    };

    load_stage(0, 0);
    load_stage(1, 32);

    for (int it = 0; it < nk; it++) {
        if (it + 1 < nk) asm volatile("cp.async.wait_group 1;");
        else             asm volatile("cp.async.wait_group 0;");
        __syncthreads();
        if (it + 2 < nk) load_stage((it + 2) % NSTAGE, (it + 2) * 32);

        unsigned* Asm = As + (it % NSTAGE) * A_TILE;
        unsigned* Bsm = Bs + (it % NSTAGE) * B_TILE;
#pragma unroll
        for (int kk = 0; kk < 4; kk++) {
            int kb = kk * 8 + qid;
            unsigned a[2][4], b[8][2];
#pragma unroll
            for (int mt = 0; mt < 2; mt++) {
                int row = wm + mt * 16 + gid;
                a[mt][0] = Asm[row * ASTR + kb];
                a[mt][1] = Asm[(row + 8) * ASTR + kb];
                a[mt][2] = Asm[row * ASTR + kb + 4];
                a[mt][3] = Asm[(row + 8) * ASTR + kb + 4];
            }
#pragma unroll
            for (int nt = 0; nt < 8; nt++) {
                int col = wn + nt * 8 + gid;
                b[nt][0] = Bsm[kb * BSTR + col];
                b[nt][1] = Bsm[(kb + 4) * BSTR + col];
            }
#pragma unroll
            for (int mt = 0; mt < 2; mt++)
#pragma unroll
                for (int nt = 0; nt < 8; nt++)
                    mma_tf32(c[mt][nt], a[mt], b[nt]);
        }
    }
    __syncthreads();
#pragma unroll
    for (int mt = 0; mt < 2; mt++) {
        int r = row0 + wm + mt * 16 + gid;
#pragma unroll
        for (int nt = 0; nt < 8; nt++) {
            int cc = col0 + wn + nt * 8 + 2 * qid;
            *(float2*)&C[(size_t)r * N + cc]       = make_float2(c[mt][nt][0], c[mt][nt][1]);
            *(float2*)&C[(size_t)(r + 8) * N + cc] = make_float2(c[mt][nt][2], c[mt][nt][3]);
        }
    }
}

__global__ __launch_bounds__(256)
void proj_gemm(const unsigned* __restrict__ xt,
               const unsigned* __restrict__ Wqs, const unsigned* __restrict__ Wks,
               const unsigned* __restrict__ Wvs, const unsigned* __restrict__ Wkg,
               const unsigned* __restrict__ Wvg,
               float* qs, float* ks, float* vs, float* kg, float* vg) {
    int id = blockIdx.x;
    const unsigned* B; float* C; int N, rb, cb;
    if (id < 768) {
        B = Wqs; C = qs; N = QW; cb = id % 12; rb = id / 12;
    } else {
        int r = id - 768;
        int w = r / 192; r -= w * 192;
        cb = r % 3; rb = r / 3; N = KVW;
        if      (w == 0) { B = Wks; C = ks; }
        else if (w == 1) { B = Wvs; C = vs; }
        else if (w == 2) { B = Wkg; C = kg; }
        else             { B = Wvg; C = vg; }
    }
    gemm_body(xt, B, C, N, rb * 128, cb * 128);
}

__global__ __launch_bounds__(256)
void out_gemm(const unsigned* __restrict__ ctxt, const unsigned* __restrict__ Wo,
              float* __restrict__ out) {
    int id = blockIdx.x;
    int cb = id % 12, rb = id / 12;
    gemm_body(ctxt, Wo, out, QW, rb * 128, cb * 128);
}

// ---------------- qg row 0 only ---------------------------------------------
__global__ __launch_bounds__(256)
void qg0_kernel(const float* __restrict__ x, const float* __restrict__ W,
                float* __restrict__ out) {
    __shared__ float xs[DM];
    int j = blockIdx.x * 256 + threadIdx.x;
    for (int k = threadIdx.x; k < DM; k += 256) xs[k] = x[k];
    __syncthreads();
    float a0 = 0.f, a1 = 0.f, a2 = 0.f, a3 = 0.f;
#pragma unroll 4
    for (int k = 0; k < DM; k += 4) {
        a0 += xs[k]     * W[(size_t)k       * QW + j];
        a1 += xs[k + 1] * W[(size_t)(k + 1) * QW + j];
        a2 += xs[k + 2] * W[(size_t)(k + 2) * QW + j];
        a3 += xs[k + 3] * W[(size_t)(k + 3) * QW + j];
    }
    out[j] = (a0 + a1) + (a2 + a3);
}

// ---------------- RoPE ------------------------------------------------------
__global__ void rope_kernel(float* __restrict__ x,
                            const float* __restrict__ cosf,
                            const float* __restrict__ sinf, int H) {
    int idx = blockIdx.x * blockDim.x + threadIdx.x;
    int total = T_LEN * H * (HD / 2);
    if (idx >= total) return;
    int p = idx % (HD / 2);
    int h = (idx / (HD / 2)) % H;
    int t = idx / ((HD / 2) * H);
    float c = cosf[t * (HD / 2) + p];
    float s = sinf[t * (HD / 2) + p];
    float* base = x + ((size_t)t * H + h) * HD + 2 * p;
    float xe = base[0], xo = base[1];
    base[0] = xe * c - xo * s;
    base[1] = xe * s + xo * c;
}

// ---------------- tensor-core flash attention (writes tf32-bit ctx) --------
#define QSTR 100
#define KSTR 100
#define VSTR 104
#define PSTR 132
#define ATTN_SMEM ((128*QSTR + 128*KSTR + 128*VSTR + 128*PSTR + 128 + 96) * 4)

__global__ __launch_bounds__(256)
void flash_attn_kernel(const float* __restrict__ qs_g, const float* __restrict__ ks_g,
                       const float* __restrict__ vs_g, const float* __restrict__ kg,
                       const float* __restrict__ vg, unsigned* __restrict__ ctxt) {
    extern __shared__ unsigned smu[];
    unsigned* Qs = smu;
    unsigned* Ks = Qs + 128 * QSTR;
    unsigned* Vs = Ks + 128 * KSTR;
    unsigned* Ps = Vs + 128 * VSTR;
    float* sg  = (float*)(Ps + 128 * PSTR);
    float* vgs = sg + 128;

    int tid = threadIdx.x, lane = tid & 31, warp = tid >> 5;
    int gid = lane >> 2, qid = lane & 3;
    int h = blockIdx.y, kvh = h >> 2;
    int q0 = blockIdx.x * 128;
    const float scale = rsqrtf((float)HD);
    int row = warp * 16 + gid;

#pragma unroll
    for (int i = 0; i < 12; i++) {
        int f = tid + 256 * i;
        int r = f / 24, c4 = (f % 24) * 4;
        float4 v = *(const float4*)&qs_g[((size_t)(q0 + r) * NH + h) * HD + c4];
        unsigned* p = &Qs[r * QSTR + c4];
        p[0] = f2tf(v.x); p[1] = f2tf(v.y); p[2] = f2tf(v.z); p[3] = f2tf(v.w);
    }
    {
        int qi = tid >> 1, half = tid & 1;
        float part = 0.f;
        const float* qrow = &qs_g[((size_t)(q0 + qi) * NH + h) * HD + half * 48];
        const float* krow = &kg[(size_t)kvh * HD + half * 48];
#pragma unroll
        for (int d = 0; d < 48; d++) part += qrow[d] * krow[d];
        part += __shfl_xor_sync(0xffffffffu, part, 1);
        if (half == 0) sg[qi] = part * scale;
    }
    if (tid < 96) vgs[tid] = vg[(size_t)kvh * HD + tid];

    float m0 = -1e9f, m1 = -1e9f, l0 = 0.f, l1 = 0.f;
    float o[12][4];
#pragma unroll
    for (int nt = 0; nt < 12; nt++)
#pragma unroll
        for (int i = 0; i < 4; i++) o[nt][i] = 0.f;

    __syncthreads();

    for (int kt = 0; kt < 3; kt++) {
        int kstart = q0 - W2 + kt * 128;
#pragma unroll
        for (int i = 0; i < 12; i++) {
            int f = tid + 256 * i;
            int r = f / 24, c4 = (f % 24) * 4;
            int krow = kstart + r;
            float4 kv = make_float4(0.f, 0.f, 0.f, 0.f), vv = kv;
            if (krow >= 0) {
                kv = *(const float4*)&ks_g[((size_t)krow * NKV + kvh) * HD + c4];
                vv = *(const float4*)&vs_g[((size_t)krow * NKV + kvh) * HD + c4];
            }
            unsigned* pk = &Ks[r * KSTR + c4];
            pk[0] = f2tf(kv.x); pk[1] = f2tf(kv.y); pk[2] = f2tf(kv.z); pk[3] = f2tf(kv.w);
            unsigned* pv = &Vs[r * VSTR + c4];
            pv[0] = f2tf(vv.x); pv[1] = f2tf(vv.y); pv[2] = f2tf(vv.z); pv[3] = f2tf(vv.w);
        }
        __syncthreads();

        float s[16][4];
#pragma unroll
        for (int nt = 0; nt < 16; nt++)
#pragma unroll
            for (int i = 0; i < 4; i++) s[nt][i] = 0.f;
#pragma unroll
        for (int ks = 0; ks < 12; ks++) {
            unsigned a[4];
            a[0] = Qs[row * QSTR + ks * 8 + qid];
            a[1] = Qs[(row + 8) * QSTR + ks * 8 + qid];
            a[2] = Qs[row * QSTR + ks * 8 + qid + 4];
            a[3] = Qs[(row + 8) * QSTR + ks * 8 + qid + 4];
#pragma unroll
            for (int nt = 0; nt < 16; nt++) {
                unsigned b[2];
                int col = nt * 8 + gid;
                b[0] = Ks[col * KSTR + ks * 8 + qid];
                b[1] = Ks[col * KSTR + ks * 8 + qid + 4];
                mma_tf32(s[nt], a, b);
            }
        }

        int t0 = q0 + row, t1 = t0 + 8;
        float tmax0 = -1e9f, tmax1 = -1e9f;
#pragma unroll
        for (int nt = 0; nt < 16; nt++) {
            int cb = kstart + nt * 8 + 2 * qid;
#pragma unroll
            for (int cc = 0; cc < 2; cc++) {
                int kp = cb + cc;
                bool v0 = (kp >= 1) && (kp <= t0) && (kp >= t0 - W2);
                bool v1 = (kp >= 1) && (kp <= t1) && (kp >= t1 - W2);
                s[nt][cc]     = v0 ? s[nt][cc] * scale     : -1e9f;
                s[nt][cc + 2] = v1 ? s[nt][cc + 2] * scale : -1e9f;
                tmax0 = fmaxf(tmax0, s[nt][cc]);
                tmax1 = fmaxf(tmax1, s[nt][cc + 2]);
            }
        }
        tmax0 = fmaxf(tmax0, __shfl_xor_sync(0xffffffffu, tmax0, 1));
        tmax0 = fmaxf(tmax0, __shfl_xor_sync(0xffffffffu, tmax0, 2));
        tmax1 = fmaxf(tmax1, __shfl_xor_sync(0xffffffffu, tmax1, 1));
        tmax1 = fmaxf(tmax1, __shfl_xor_sync(0xffffffffu, tmax1, 2));
        float mn0 = fmaxf(m0, tmax0), mn1 = fmaxf(m1, tmax1);
        float corr0 = __expf(m0 - mn0), corr1 = __expf(m1 - mn1);
        l0 *= corr0; l1 *= corr1;
#pragma unroll
        for (int nt = 0; nt < 12; nt++) {
            o[nt][0] *= corr0; o[nt][1] *= corr0;
            o[nt][2] *= corr1; o[nt][3] *= corr1;
        }
        float sum0 = 0.f, sum1 = 0.f;
#pragma unroll
        for (int nt = 0; nt < 16; nt++) {
            int cb = nt * 8 + 2 * qid;
#pragma unroll
            for (int cc = 0; cc < 2; cc++) {
                float p0 = __expf(s[nt][cc] - mn0);
                float p1 = __expf(s[nt][cc + 2] - mn1);
                sum0 += p0; sum1 += p1;
                Ps[row * PSTR + cb + cc]       = f2tf(p0);
                Ps[(row + 8) * PSTR + cb + cc] = f2tf(p1);
            }
        }
        sum0 += __shfl_xor_sync(0xffffffffu, sum0, 1);
        sum0 += __shfl_xor_sync(0xffffffffu, sum0, 2);
        sum1 += __shfl_xor_sync(0xffffffffu, sum1, 1);
        sum1 += __shfl_xor_sync(0xffffffffu, sum1, 2);
        l0 += sum0; l1 += sum1;
        m0 = mn0; m1 = mn1;
        __syncwarp();

#pragma unroll
        for (int ks = 0; ks < 16; ks++) {
            unsigned a[4];
            a[0] = Ps[row * PSTR + ks * 8 + qid];
            a[1] = Ps[(row + 8) * PSTR + ks * 8 + qid];
            a[2] = Ps[row * PSTR + ks * 8 + qid + 4];
            a[3] = Ps[(row + 8) * PSTR + ks * 8 + qid + 4];
#pragma unroll
            for (int nt = 0; nt < 12; nt++) {
                unsigned b[2];
                int col = nt * 8 + gid;
                b[0] = Vs[(ks * 8 + qid) * VSTR + col];
                b[1] = Vs[(ks * 8 + qid + 4) * VSTR + col];
                mma_tf32(o[nt], a, b);
            }
        }
        __syncthreads();
    }

    // global key (position 0) + tf32-bit epilogue
    {
        float sg0 = sg[row], sg1 = sg[row + 8];
        float mn0 = fmaxf(m0, sg0), mn1 = fmaxf(m1, sg1);
        float corr0 = __expf(m0 - mn0), corr1 = __expf(m1 - mn1);
        float pg0 = __expf(sg0 - mn0), pg1 = __expf(sg1 - mn1);
        l0 = l0 * corr0 + pg0;
        l1 = l1 * corr1 + pg1;
        float inv0 = 1.f / l0, inv1 = 1.f / l1;
        int t0 = q0 + row, t1 = t0 + 8;
#pragma unroll
        for (int nt = 0; nt < 12; nt++) {
            int d = nt * 8 + 2 * qid;
            float v0 = vgs[d], v1 = vgs[d + 1];
            uint2 r0 = make_uint2(f2tf((o[nt][0] * corr0 + pg0 * v0) * inv0),
                                  f2tf((o[nt][1] * corr0 + pg0 * v1) * inv0));
            uint2 r1 = make_uint2(f2tf((o[nt][2] * corr1 + pg1 * v0) * inv1),
                                  f2tf((o[nt][3] * corr1 + pg1 * v1) * inv1));
            *(uint2*)&ctxt[((size_t)t0 * NH + h) * HD + d] = r0;
            *(uint2*)&ctxt[((size_t)t1 * NH + h) * HD + d] = r1;
        }
    }
}

// ---------------- global row: q@pos0 (qg) over all T kg keys --------------
__global__ __launch_bounds__(192)
void global_row_kernel(const float* __restrict__ qg, const float* __restrict__ kg,
                       const float* __restrict__ vg, unsigned* __restrict__ ctxt) {
    __shared__ float p[T_LEN];
    __shared__ float red[256];
    int h = blockIdx.x, kvh = h >> 2, tid = threadIdx.x;
    float q[HD];
#pragma unroll
    for (int d = 0; d < HD; d++) q[d] = qg[(size_t)h * HD + d];
    const float scale = rsqrtf((float)HD);

    float lm = -1e30f;
    for (int t = tid; t < T_LEN; t += 192) {
        float s = 0.f;
#pragma unroll
        for (int d = 0; d < HD; d++) s += q[d] * kg[((size_t)t * NKV + kvh) * HD + d];
        s *= scale;
        p[t] = s;
        lm = fmaxf(lm, s);
    }
    red[tid] = lm;
    if (tid < 64) red[192 + tid] = -1e30f;
    __syncthreads();
    for (int o = 128; o > 0; o >>= 1) {
        if (tid < o) red[tid] = fmaxf(red[tid], red[tid + o]);
        __syncthreads();
    }
    float m = red[0];
    __syncthreads();

    float ll = 0.f;
    for (int t = tid; t < T_LEN; t += 192) {
        float e = __expf(p[t] - m);
        p[t] = e;
        ll += e;
    }
    red[tid] = ll;
    if (tid < 64) red[192 + tid] = 0.f;
    __syncthreads();
    for (int o = 128; o > 0; o >>= 1) {
        if (tid < o) red[tid] += red[tid + o];
        __syncthreads();
    }
    float inv = 1.f / red[0];
    __syncthreads();

    int d = tid % 96, g = tid / 96;
    float acc0 = 0.f, acc1 = 0.f, acc2 = 0.f, acc3 = 0.f;
    for (int t = g; t < T_LEN; t += 8) {
        acc0 += p[t]     * vg[((size_t)t       * NKV + kvh) * HD + d];
        acc1 += p[t + 2] * vg[((size_t)(t + 2) * NKV + kvh) * HD + d];
        acc2 += p[t + 4] * vg[((size_t)(t + 4) * NKV + kvh) * HD + d];
        acc3 += p[t + 6] * vg[((size_t)(t + 6) * NKV + kvh) * HD + d];
    }
    red[tid] = acc0 + acc1 + acc2 + acc3;
    __syncthreads();
    if (g == 0) ctxt[(size_t)h * HD + d] = f2tf((red[d] + red[96 + d]) * inv);
}

// ---------------- launch ---------------------------------------------------
extern "C" void kernel_launch(void* const* d_in, const int* in_sizes, int n_in,
                              void* d_out, int out_size) {
    const float* x    = (const float*)d_in[0];
    const float* cosf = (const float*)d_in[1];
    const float* sinf = (const float*)d_in[2];
    // d_in[3] = position_ids (arange, unused)
    const float* W_qs = (const float*)d_in[4];
    const float* W_ks = (const float*)d_in[5];
    const float* W_vs = (const float*)d_in[6];
    const float* W_qg = (const float*)d_in[7];
    const float* W_kg = (const float*)d_in[8];
    const float* W_vg = (const float*)d_in[9];
    const float* W_o  = (const float*)d_in[10];
    float* out = (float*)d_out;

    float *qs, *ks, *vs, *kg, *vg, *qg0;
    unsigned *xt, *ctxt, *wqst, *wkst, *wvst, *wkgt, *wvgt, *wot;
    cudaGetSymbolAddress((void**)&qs,   g_qs);
    cudaGetSymbolAddress((void**)&ks,   g_ks);
    cudaGetSymbolAddress((void**)&vs,   g_vs);
    cudaGetSymbolAddress((void**)&kg,   g_kg);
    cudaGetSymbolAddress((void**)&vg,   g_vg);
    cudaGetSymbolAddress((void**)&qg0,  g_qg0);
    cudaGetSymbolAddress((void**)&xt,   g_xt);
    cudaGetSymbolAddress((void**)&ctxt, g_ctxt);
    cudaGetSymbolAddress((void**)&wqst, g_wqst);
    cudaGetSymbolAddress((void**)&wkst, g_wkst);
    cudaGetSymbolAddress((void**)&wvst, g_wvst);
    cudaGetSymbolAddress((void**)&wkgt, g_wkgt);
    cudaGetSymbolAddress((void**)&wvgt, g_wvgt);
    cudaGetSymbolAddress((void**)&wot,  g_wot);

    cudaFuncSetAttribute(proj_gemm, cudaFuncAttributeMaxDynamicSharedMemorySize, GEMM_SMEM);
    cudaFuncSetAttribute(out_gemm,  cudaFuncAttributeMaxDynamicSharedMemorySize, GEMM_SMEM);
    cudaFuncSetAttribute(flash_attn_kernel, cudaFuncAttributeMaxDynamicSharedMemorySize, ATTN_SMEM);

    // ---- pack fp32 -> tf32 bits (elementwise, layout-preserving) ----
    int xq = T_LEN * DM / 4;
    int wq = DM * QW / 4, wn = DM * KVW / 4;
    pack_tf32<<<(xq + 255) / 256, 256>>>(x, xt, xq);
    pack_tf32<<<(wq + 255) / 256, 256>>>(W_qs, wqst, wq);
    pack_tf32<<<(wn + 255) / 256, 256>>>(W_ks, wkst, wn);
    pack_tf32<<<(wn + 255) / 256, 256>>>(W_vs, wvst, wn);
    pack_tf32<<<(wn + 255) / 256, 256>>>(W_kg, wkgt, wn);
    pack_tf32<<<(wn + 255) / 256, 256>>>(W_vg, wvgt, wn);
    pack_tf32<<<(wq + 255) / 256, 256>>>(W_o,  wot,  wq);

    proj_gemm<<<1536, 256, GEMM_SMEM>>>(xt, wqst, wkst, wvst, wkgt, wvgt,
                                        qs, ks, vs, kg, vg);
    qg0_kernel<<<QW / 256, 256>>>(x, W_qg, qg0);

    int pairs16 = T_LEN * NH * (HD / 2);
    int pairs4  = T_LEN * NKV * (HD / 2);
    rope_kernel<<<(pairs16 + 255) / 256, 256>>>(qs, cosf, sinf, NH);
    rope_kernel<<<(pairs4  + 255) / 256, 256>>>(ks, cosf, sinf, NKV);
    rope_kernel<<<(pairs4  + 255) / 256, 256>>>(kg, cosf, sinf, NKV);

    flash_attn_kernel<<<dim3(T_LEN / 128, NH), 256, ATTN_SMEM>>>(qs, ks, vs, kg, vg, ctxt);

    global_row_kernel<<<NH, 192>>>(qg0, kg, vg, ctxt);

    out_gemm<<<768, 256, GEMM_SMEM>>>(ctxt, wot, out);
}